// round 14
// baseline (speedup 1.0000x reference)
#include <cuda_runtime.h>
#include <cuda_bf16.h>
#include <cuda_fp16.h>

#define Bn   4
#define Pn   900
#define Hn   8
#define DKn  64
#define DMn  512
#define PP2  (Pn*Pn)      // 810000
#define BHn  (Bn*Hn)      // 32

typedef unsigned long long u64_t;

// ---- fp16 m16n8k16 MMA ----
__device__ __forceinline__ void mma_f16_k16(float* c, const unsigned* a, const unsigned* b) {
    asm("mma.sync.aligned.m16n8k16.row.col.f32.f16.f16.f32 "
        "{%0,%1,%2,%3}, {%4,%5,%6,%7}, {%8,%9}, {%0,%1,%2,%3};"
        : "+f"(c[0]), "+f"(c[1]), "+f"(c[2]), "+f"(c[3])
        : "r"(a[0]), "r"(a[1]), "r"(a[2]), "r"(a[3]), "r"(b[0]), "r"(b[1]));
}
// fragment held as two u64: l0 = (a0|a2<<32) row qr, l1 = (a1|a3<<32) row qr+8
__device__ __forceinline__ void mma_from(float* c, u64_t l0, u64_t l1, const unsigned* b) {
    unsigned a[4] = { (unsigned)l0, (unsigned)l1,
                      (unsigned)(l0 >> 32), (unsigned)(l1 >> 32) };
    mma_f16_k16(c, a, b);
}
__device__ __forceinline__ unsigned packh2(float x, float y) {
    __half2 h = __floats2half2_rn(x, y);
    return *reinterpret_cast<unsigned*>(&h);
}
// split (v0,v1) into fp16 hi pair + fp16 lo pair (11+11 mantissa bits)
__device__ __forceinline__ void split2(float v0, float v1, unsigned& hi, unsigned& lo) {
    __half h0 = __float2half_rn(v0), h1 = __float2half_rn(v1);
    float r0 = v0 - __half2float(h0), r1 = v1 - __half2float(h1);
    __half2 H = __halves2half2(h0, h1);
    hi = *reinterpret_cast<unsigned*>(&H);
    lo = packh2(r0, r1);
}

// order-preserving float->uint
__device__ __forceinline__ unsigned ord_f(float v) {
    unsigned b = __float_as_uint(v);
    return (b & 0x80000000u) ? ~b : (b | 0x80000000u);
}
__device__ __forceinline__ u64_t amax_key(float v, int p) {
    return ((u64_t)ord_f(v) << 32) | (u64_t)(0xFFFFFFFFu - (unsigned)p);
}

// ---- scratch (static device allocations; no runtime alloc) ----
__device__ unsigned g_Qh[BHn*Pn*32];
__device__ unsigned g_Ql[BHn*Pn*32];
__device__ unsigned g_Kh[BHn*Pn*32];
__device__ unsigned g_Kl[BHn*Pn*32];
__device__ float    g_S [BHn*PP2];
__device__ u64_t    g_AMX[BHn*Pn];
__device__ unsigned g_ATT[Bn*4*PP2];
__device__ float    g_PART[Bn*Hn*Pn*64];

// ============================================================
// K1: projection GEMM (Q and K via blockIdx.z), fp16 3-MMA split.
// ============================================================
__global__ __launch_bounds__(256) void proj_kernel(const float* __restrict__ query,
                                                   const float* __restrict__ key_t,
                                                   const float* __restrict__ Wq,
                                                   const float* __restrict__ bq,
                                                   const float* __restrict__ Wk,
                                                   const float* __restrict__ bk)
{
    __shared__ unsigned Ahi[64*20], Alo[64*20], Whi[64*20], Wlo[64*20];
    const int z = blockIdx.z;
    const float* A    = z ? key_t : query;
    const float* W    = z ? Wk : Wq;
    const float* bias = z ? bk : bq;
    unsigned* outh = z ? g_Kh : g_Qh;
    unsigned* outl = z ? g_Kl : g_Ql;

    const int bm = blockIdx.y * 64;
    const int bn = blockIdx.x * 64;
    const int tid = threadIdx.x;
    const int lane = tid & 31, wid = tid >> 5;
    const int qr = lane >> 2, icb = lane & 3;
    const int m0 = (wid & 3) * 16;
    const int n0 = (wid >> 2) * 32;
    float acc[4][4] = {};

    for (int k0 = 0; k0 < DMn; k0 += 32) {
        #pragma unroll
        for (int i = tid; i < 1024; i += 256) {
            int r = i >> 4, c2 = i & 15;
            int m = bm + r;
            int kc = k0 + 2*c2;
            float a0 = 0.f, a1 = 0.f;
            if (m < Bn*Pn) {
                a0 = A[(size_t)m*DMn + kc];
                a1 = A[(size_t)m*DMn + kc + 1];
            }
            float w0 = W[(size_t)(bn + r)*DMn + kc];
            float w1 = W[(size_t)(bn + r)*DMn + kc + 1];
            split2(a0, a1, Ahi[r*20 + c2], Alo[r*20 + c2]);
            split2(w0, w1, Whi[r*20 + c2], Wlo[r*20 + c2]);
        }
        __syncthreads();
        #pragma unroll
        for (int ks = 0; ks < 2; ks++) {
            int b8 = ks*8;
            unsigned ah[4], al[4];
            int rA = (m0 + qr)*20 + b8 + icb;
            int rB = (m0 + qr + 8)*20 + b8 + icb;
            ah[0] = Ahi[rA];     ah[1] = Ahi[rB];
            ah[2] = Ahi[rA + 4]; ah[3] = Ahi[rB + 4];
            al[0] = Alo[rA];     al[1] = Alo[rB];
            al[2] = Alo[rA + 4]; al[3] = Alo[rB + 4];
            #pragma unroll
            for (int j = 0; j < 4; j++) {
                int rK = (n0 + j*8 + qr)*20 + b8 + icb;
                unsigned bh_[2] = { Whi[rK], Whi[rK + 4] };
                unsigned bl_[2] = { Wlo[rK], Wlo[rK + 4] };
                mma_f16_k16(acc[j], ah, bh_);
                mma_f16_k16(acc[j], ah, bl_);
                mma_f16_k16(acc[j], al, bh_);
            }
        }
        __syncthreads();
    }

    const int mA = bm + m0 + qr, mB = mA + 8;
    #pragma unroll
    for (int j = 0; j < 4; j++) {
        int na = bn + n0 + j*8 + 2*icb;
        int h = na >> 6, c2 = (na & 63) >> 1;
        if (mA < Bn*Pn) {
            int b = mA / Pn, p = mA % Pn;
            unsigned hi, lo;
            split2(acc[j][0] + bias[na], acc[j][1] + bias[na+1], hi, lo);
            size_t idx = ((size_t)(b*Hn + h)*Pn + p)*32 + c2;
            outh[idx] = hi; outl[idx] = lo;
        }
        if (mB < Bn*Pn) {
            int b = mB / Pn, p = mB % Pn;
            unsigned hi, lo;
            split2(acc[j][2] + bias[na], acc[j][3] + bias[na+1], hi, lo);
            size_t idx = ((size_t)(b*Hn + h)*Pn + p)*32 + c2;
            outh[idx] = hi; outl[idx] = lo;
        }
    }
}

// ============================================================
// K2: scores via fp16 3-MMA split (k16) + fused argmax.
// ============================================================
__global__ __launch_bounds__(256) void scores_kernel()
{
    __shared__ unsigned Qhi[64*36], Qlo[64*36], Khi[64*36], Klo[64*36];

    const int bh = blockIdx.z;
    const int p0 = blockIdx.y*64, q0 = blockIdx.x*64;
    const int tid = threadIdx.x;
    const int lane = tid & 31, wid = tid >> 5;
    const int qr = lane >> 2, icb = lane & 3;

    #pragma unroll
    for (int i = tid; i < 2048; i += 256) {
        int r = i >> 5, c2 = i & 31;
        unsigned qh = 0, ql = 0, kh = 0, kl = 0;
        if (p0 + r < Pn) {
            size_t idx = ((size_t)bh*Pn + p0 + r)*32 + c2;
            qh = g_Qh[idx]; ql = g_Ql[idx];
        }
        if (q0 + r < Pn) {
            size_t idx = ((size_t)bh*Pn + q0 + r)*32 + c2;
            kh = g_Kh[idx]; kl = g_Kl[idx];
        }
        Qhi[r*36 + c2] = qh; Qlo[r*36 + c2] = ql;
        Khi[r*36 + c2] = kh; Klo[r*36 + c2] = kl;
    }
    __syncthreads();

    const int m0 = (wid & 3) * 16;
    const int n0 = (wid >> 2) * 32;
    float acc[4][4] = {};

    #pragma unroll
    for (int ks = 0; ks < 4; ks++) {
        int b8 = ks*8;
        unsigned ah[4], al[4];
        int rA = (m0 + qr)*36 + b8 + icb;
        int rB = (m0 + qr + 8)*36 + b8 + icb;
        ah[0] = Qhi[rA];     ah[1] = Qhi[rB];
        ah[2] = Qhi[rA + 4]; ah[3] = Qhi[rB + 4];
        al[0] = Qlo[rA];     al[1] = Qlo[rB];
        al[2] = Qlo[rA + 4]; al[3] = Qlo[rB + 4];
        #pragma unroll
        for (int j = 0; j < 4; j++) {
            int rK = (n0 + j*8 + qr)*36 + b8 + icb;
            unsigned bh_[2] = { Khi[rK], Khi[rK + 4] };
            unsigned bl_[2] = { Klo[rK], Klo[rK + 4] };
            mma_f16_k16(acc[j], ah, bh_);
            mma_f16_k16(acc[j], ah, bl_);
            mma_f16_k16(acc[j], al, bh_);
        }
    }

    float* Sb = g_S + (size_t)bh*PP2;
    const int pA = p0 + m0 + qr, pB = pA + 8;
    const bool vA = pA < Pn, vB = pB < Pn;
    #pragma unroll
    for (int j = 0; j < 4; j++) {
        int qa = q0 + n0 + j*8 + 2*icb;
        int qb = qa + 1;
        if (vA) {
            if (qa < Pn) Sb[pA*Pn + qa] = acc[j][0];
            if (qb < Pn) Sb[pA*Pn + qb] = acc[j][1];
        }
        if (vB) {
            if (qa < Pn) Sb[pB*Pn + qa] = acc[j][2];
            if (qb < Pn) Sb[pB*Pn + qb] = acc[j][3];
        }
        u64_t ka = 0, kb = 0;
        if (vA) { ka = amax_key(acc[j][0], pA); kb = amax_key(acc[j][1], pA); }
        if (vB) {
            u64_t t = amax_key(acc[j][2], pB); if (t > ka) ka = t;
            t = amax_key(acc[j][3], pB);       if (t > kb) kb = t;
        }
        #pragma unroll
        for (int m = 4; m <= 16; m <<= 1) {
            u64_t ta = __shfl_xor_sync(0xFFFFFFFFu, ka, m);
            u64_t tb = __shfl_xor_sync(0xFFFFFFFFu, kb, m);
            if (ta > ka) ka = ta;
            if (tb > kb) kb = tb;
        }
        if (qr == 0) {
            if (qa < Pn) atomicMax(&g_AMX[bh*Pn + qa], ka);
            if (qb < Pn) atomicMax(&g_AMX[bh*Pn + qb], kb);
        }
    }
}

// ============================================================
// K4: gaussian + scale + softmax; warp = one p-row of a CHANNEL PAIR.
// ============================================================
__global__ __launch_bounds__(256) void modsm_kernel()
{
    __shared__ float sT[900];
    __shared__ unsigned char sFX0[900], sFY0[900], sFX1[900], sFY1[900];
    const int bj = blockIdx.y;
    const int b = bj >> 2, j = bj & 3;
    const int bh0 = b*Hn + 2*j, bh1 = bh0 + 1;
    const int p0 = blockIdx.x * 8;
    const int tid = threadIdx.x, lane = tid & 31, wrp = tid >> 5;

    for (int i = tid; i < 900; i += 256) {
        int a = i / 30, bc = i - (i/30)*30;
        float d = (-1.f + (2.f/29.f)*(float)a) - (float)bc;
        sT[i] = __expf(-d*d*0.02f);
        unsigned id0 = 0xFFFFFFFFu - (unsigned)(g_AMX[bh0*Pn + i] & 0xFFFFFFFFu);
        unsigned id1 = 0xFFFFFFFFu - (unsigned)(g_AMX[bh1*Pn + i] & 0xFFFFFFFFu);
        sFX0[i] = (unsigned char)(id0 % 30); sFY0[i] = (unsigned char)(id0 / 30);
        sFX1[i] = (unsigned char)(id1 % 30); sFY1[i] = (unsigned char)(id1 / 30);
    }
    __syncthreads();

    const int p = p0 + wrp;
    if (p >= Pn) return;
    const float* S0 = g_S + (size_t)bh0*PP2 + (size_t)p*Pn;
    const float* S1 = g_S + (size_t)bh1*PP2 + (size_t)p*Pn;
    const float* Tx = sT + (p % 30)*30;
    const float* Ty = sT + (p / 30)*30;

    float v0[29], v1[29];
    float m0 = -1e30f, m1 = -1e30f;
    #pragma unroll
    for (int i = 0; i < 29; i++) {
        int q = lane + i*32;
        if (q < Pn) {
            float s0 = S0[q], s1 = S1[q];
            float g0 = Tx[sFX0[q]] * Ty[sFY0[q]];
            float g1 = Tx[sFX1[q]] * Ty[sFY1[q]];
            v0[i] = g0 * s0 * 0.125f;
            v1[i] = g1 * s1 * 0.125f;
            m0 = fmaxf(m0, v0[i]);
            m1 = fmaxf(m1, v1[i]);
        } else { v0[i] = -1e30f; v1[i] = -1e30f; }
    }
    #pragma unroll
    for (int m = 16; m > 0; m >>= 1) {
        m0 = fmaxf(m0, __shfl_xor_sync(0xFFFFFFFFu, m0, m));
        m1 = fmaxf(m1, __shfl_xor_sync(0xFFFFFFFFu, m1, m));
    }

    float sum0 = 0.f, sum1 = 0.f;
    #pragma unroll
    for (int i = 0; i < 29; i++) {
        float e0 = __expf(v0[i] - m0);
        float e1 = __expf(v1[i] - m1);
        v0[i] = e0; v1[i] = e1;
        if (lane + i*32 < Pn) { sum0 += e0; sum1 += e1; }
    }
    #pragma unroll
    for (int m = 16; m > 0; m >>= 1) {
        sum0 += __shfl_xor_sync(0xFFFFFFFFu, sum0, m);
        sum1 += __shfl_xor_sync(0xFFFFFFFFu, sum1, m);
    }
    const float inv0 = 1.f / sum0, inv1 = 1.f / sum1;
    unsigned* dst = g_ATT + (size_t)bj*PP2 + (size_t)p*Pn;
    #pragma unroll
    for (int i = 0; i < 29; i++) {
        int q = lane + i*32;
        if (q < Pn) dst[q] = packh2(v0[i]*inv0, v1[i]*inv1);
    }
}

// ============================================================
// K5: FUSED conv1+conv2+value-einsum, fp16 MMA.
// Phase 2: per-warp register cache of 3 mid-rows of A-fragments,
// walked over 4 consecutive oy tiles -> ~2x less smem traffic.
// sMid: u64 [plane(kc*4+icb)][pos], stride 612 (bank-verified).
// ============================================================
#define FT_Y   16
#define FT_X   32
#define MID_W  34
#define MID_N  612
#define IN_W   36
#define IN_N   720
#define PIN    728
#define SMEM_FUSED (4*PIN*4 + 8*MID_N*8)   // 11648 + 39168 = 50816 B

__device__ __forceinline__ void load_row(u64_t (&D)[3][2][2], const u64_t* sMid64,
                                         int mr, int xb, int qr, int icb) {
    #pragma unroll
    for (int kx = 0; kx < 3; kx++)
        #pragma unroll
        for (int kc = 0; kc < 2; kc++) {
            int bs = (kc*4 + icb)*MID_N + mr*MID_W + xb + kx + qr;
            D[kx][kc][0] = sMid64[bs];
            D[kx][kc][1] = sMid64[bs + 8];
        }
}

__global__ __launch_bounds__(256) void fused_conv_kernel(const float* __restrict__ w1,
                                                         const float* __restrict__ b1,
                                                         const float* __restrict__ w2,
                                                         const float* __restrict__ b2,
                                                         const float* __restrict__ value)
{
    extern __shared__ unsigned dsm[];
    unsigned* sIn   = dsm;                                        // 4 ic-pairs x 728
    u64_t*    sMid64 = reinterpret_cast<u64_t*>(dsm + 4*PIN);     // 8 planes x 612
    __shared__ float sB1[32];
    __shared__ float sB2[8];
    __shared__ float sVal[32];

    const int n  = blockIdx.z;
    const int X0 = blockIdx.x * FT_X;
    const int Y0 = blockIdx.y * FT_Y;
    const int tid  = threadIdx.x;
    const int lane = tid & 31, wid = tid >> 5;
    const int qr = lane >> 2, icb = lane & 3;

    if (tid < 32) {
        sB1[tid] = b1[tid];
        sVal[tid] = (X0 + tid < Pn) ? value[n*Pn + X0 + tid] : 0.f;
    }
    if (tid < 8)  sB2[tid] = b2[tid];

    for (int i = tid; i < IN_N; i += 256) {
        int r = i / IN_W, c = i - r*IN_W;
        int gy = Y0 - 2 + r, gx = X0 - 2 + c;
        bool ok = (gy >= 0 && gy < Pn && gx >= 0 && gx < Pn);
        size_t base = (size_t)gy*Pn + gx;
        #pragma unroll
        for (int j = 0; j < 4; j++)
            sIn[j*PIN + i] = ok ? g_ATT[(size_t)(n*4 + j)*PP2 + base] : 0u;
    }

    unsigned bw[5][4][2];
    #pragma unroll
    for (int p = 0; p < 5; p++) {
        int sA = 2*p, sB = 2*p + 1;
        #pragma unroll
        for (int g = 0; g < 4; g++) {
            int oc = g*8 + qr;
            bw[p][g][0] = packh2(w1[(oc*8 + 2*icb)*9 + sA],
                                 w1[(oc*8 + 2*icb + 1)*9 + sA]);
            bw[p][g][1] = (sB < 9) ? packh2(w1[(oc*8 + 2*icb)*9 + sB],
                                            w1[(oc*8 + 2*icb + 1)*9 + sB])
                                   : 0u;
        }
    }
    __syncthreads();

    // ---- phase 1: conv1 -> sMid64 ----
    for (int t = wid; t < 39; t += 8) {
        int pr0 = t*16 + qr;
        int pr1 = pr0 + 8;
        int q0 = pr0 < MID_N ? pr0 : MID_N - 1;
        int q1 = pr1 < MID_N ? pr1 : MID_N - 1;
        int my0 = q0 / MID_W, mx0 = q0 - my0*MID_W;
        int my1 = q1 / MID_W, mx1 = q1 - my1*MID_W;
        int base0 = my0*IN_W + mx0;
        int base1 = my1*IN_W + mx1;
        float acc[4][4] = {};
        #pragma unroll
        for (int p = 0; p < 5; p++) {
            int sA = 2*p, sB = 2*p + 1;
            int offA = (sA/3)*IN_W + (sA - (sA/3)*3);
            int offB = (sB < 9) ? (sB/3)*IN_W + (sB - (sB/3)*3) : offA;
            unsigned a[4];
            a[0] = sIn[icb*PIN + base0 + offA];
            a[1] = sIn[icb*PIN + base1 + offA];
            a[2] = sIn[icb*PIN + base0 + offB];
            a[3] = sIn[icb*PIN + base1 + offB];
            #pragma unroll
            for (int g = 0; g < 4; g++) mma_f16_k16(acc[g], a, bw[p][g]);
        }
        bool s0 = pr0 < MID_N, s1 = pr1 < MID_N;
        int gy0 = Y0 - 1 + my0, gx0 = X0 - 1 + mx0;
        int gy1 = Y0 - 1 + my1, gx1 = X0 - 1 + mx1;
        bool in0 = (gy0 >= 0 && gy0 < Pn && gx0 >= 0 && gx0 < Pn);
        bool in1 = (gy1 >= 0 && gy1 < Pn && gx1 >= 0 && gx1 < Pn);
        // store paired-g u64 per (kc, row): plane kc*4+icb, low = oc 16kc+2icb pair, high = +8
        #pragma unroll
        for (int kc = 0; kc < 2; kc++) {
            int ocL = kc*16 + 2*icb;
            int ocH = ocL + 8;
            if (s0) {
                float vL0 = in0 ? fmaxf(acc[2*kc][0]   + sB1[ocL],   0.f) : 0.f;
                float vL1 = in0 ? fmaxf(acc[2*kc][1]   + sB1[ocL+1], 0.f) : 0.f;
                float vH0 = in0 ? fmaxf(acc[2*kc+1][0] + sB1[ocH],   0.f) : 0.f;
                float vH1 = in0 ? fmaxf(acc[2*kc+1][1] + sB1[ocH+1], 0.f) : 0.f;
                sMid64[(kc*4 + icb)*MID_N + q0] =
                    (u64_t)packh2(vL0, vL1) | ((u64_t)packh2(vH0, vH1) << 32);
            }
            if (s1) {
                float vL2 = in1 ? fmaxf(acc[2*kc][2]   + sB1[ocL],   0.f) : 0.f;
                float vL3 = in1 ? fmaxf(acc[2*kc][3]   + sB1[ocL+1], 0.f) : 0.f;
                float vH2 = in1 ? fmaxf(acc[2*kc+1][2] + sB1[ocH],   0.f) : 0.f;
                float vH3 = in1 ? fmaxf(acc[2*kc+1][3] + sB1[ocH+1], 0.f) : 0.f;
                sMid64[(kc*4 + icb)*MID_N + q1] =
                    (u64_t)packh2(vL2, vL3) | ((u64_t)packh2(vH2, vH3) << 32);
            }
        }
    }
    __syncthreads();

    unsigned bw2[9][2][2];
    #pragma unroll
    for (int s = 0; s < 9; s++)
        #pragma unroll
        for (int kc = 0; kc < 2; kc++) {
            bw2[s][kc][0] = packh2(w2[(qr*32 + 16*kc + 2*icb)*9 + s],
                                   w2[(qr*32 + 16*kc + 2*icb + 1)*9 + s]);
            bw2[s][kc][1] = packh2(w2[(qr*32 + 16*kc + 8 + 2*icb)*9 + s],
                                   w2[(qr*32 + 16*kc + 8 + 2*icb + 1)*9 + s]);
        }

    // ---- phase 2: conv2 + value reduction, register row-cache ----
    const int xh  = wid >> 2;            // x-half 0/1
    const int oy0 = (wid & 3) * 4;       // 4 consecutive oy per warp
    const int xb  = xh * 16;
    const int ox0 = xb + qr, ox1 = ox0 + 8;
    const int xp  = blockIdx.x*2 + xh;
    const int oc  = 2*icb;
    const float bb0 = sB2[oc], bb1 = sB2[oc+1];
    const float svA = sVal[ox0], svB = sVal[ox1];

    u64_t RA[3][2][2], RB[3][2][2], RC[3][2][2];
    load_row(RA, sMid64, oy0,     xb, qr, icb);
    load_row(RB, sMid64, oy0 + 1, xb, qr, icb);

    #pragma unroll
    for (int i = 0; i < 4; i++) {
        int oy = oy0 + i;
        load_row(RC, sMid64, oy + 2, xb, qr, icb);
        float acc[4] = {};
        #pragma unroll
        for (int kx = 0; kx < 3; kx++)
            #pragma unroll
            for (int kc = 0; kc < 2; kc++) {
                mma_from(acc, RA[kx][kc][0], RA[kx][kc][1], bw2[kx][kc]);
                mma_from(acc, RB[kx][kc][0], RB[kx][kc][1], bw2[3 + kx][kc]);
                mma_from(acc, RC[kx][kc][0], RC[kx][kc][1], bw2[6 + kx][kc]);
            }

        float r0 = fmaxf(acc[0] + bb0, 0.f);
        float r1 = fmaxf(acc[1] + bb1, 0.f);
        float r2 = fmaxf(acc[2] + bb0, 0.f);
        float r3 = fmaxf(acc[3] + bb1, 0.f);
        float s0 = r0*svA + r2*svB;
        float s1 = r1*svA + r3*svB;
        #pragma unroll
        for (int m = 4; m <= 16; m <<= 1) {
            s0 += __shfl_xor_sync(0xFFFFFFFFu, s0, m);
            s1 += __shfl_xor_sync(0xFFFFFFFFu, s1, m);
        }
        int y = Y0 + oy;
        if (qr == 0 && y < Pn) {
            g_PART[((size_t)(n*Hn + oc    )*Pn + y)*64 + xp] = s0;
            g_PART[((size_t)(n*Hn + oc + 1)*Pn + y)*64 + xp] = s1;
        }
        // rotate row cache
        #pragma unroll
        for (int kx = 0; kx < 3; kx++)
            #pragma unroll
            for (int kc = 0; kc < 2; kc++)
                #pragma unroll
                for (int l = 0; l < 2; l++) {
                    RA[kx][kc][l] = RB[kx][kc][l];
                    RB[kx][kc][l] = RC[kx][kc][l];
                }
    }
}

// ============================================================
// K6: reduce partials -> out[b,p] = mean_h sum_xp
// ============================================================
__global__ __launch_bounds__(128) void reduce_kernel(float* __restrict__ out)
{
    const int bp = blockIdx.x;
    const int b = bp / Pn, p = bp % Pn;
    const int tid = threadIdx.x;
    float s = 0.f;
    for (int i = tid; i < 512; i += 128) {
        int h = i >> 6, xp = i & 63;
        if (xp < 58)
            s += g_PART[((size_t)(b*Hn + h)*Pn + p)*64 + xp];
    }
    __shared__ float red[128];
    red[tid] = s; __syncthreads();
    for (int st = 64; st > 0; st >>= 1) {
        if (tid < st) red[tid] += red[tid + st];
        __syncthreads();
    }
    if (tid == 0) out[bp] = red[0] * 0.125f;
}

// ============================================================
extern "C" void kernel_launch(void* const* d_in, const int* in_sizes, int n_in,
                              void* d_out, int out_size)
{
    const float* query = (const float*)d_in[0];
    const float* key_t = (const float*)d_in[1];
    const float* value = (const float*)d_in[2];
    const float* Wq    = (const float*)d_in[3];
    const float* bq    = (const float*)d_in[4];
    const float* Wk    = (const float*)d_in[5];
    const float* bk    = (const float*)d_in[6];
    const float* c1w   = (const float*)d_in[7];
    const float* c1b   = (const float*)d_in[8];
    const float* c2w   = (const float*)d_in[9];
    const float* c2b   = (const float*)d_in[10];
    float* out = (float*)d_out;

    static int smem_set = 0;
    if (!smem_set) {
        cudaFuncSetAttribute(fused_conv_kernel,
                             cudaFuncAttributeMaxDynamicSharedMemorySize, SMEM_FUSED);
        smem_set = 1;
    }

    proj_kernel<<<dim3(8, 57, 2), 256>>>(query, key_t, Wq, bq, Wk, bk);
    scores_kernel<<<dim3(15, 15, 32), 256>>>();
    modsm_kernel<<<dim3(113, 16), 256>>>();
    fused_conv_kernel<<<dim3(29, 57, 4), 256, SMEM_FUSED>>>(c1w, c1b, c2w, c2b, value);
    reduce_kernel<<<dim3(Bn*Pn), 128>>>(out);
}

// round 15
// speedup vs baseline: 1.4973x; 1.4973x over previous
#include <cuda_runtime.h>
#include <cuda_bf16.h>
#include <cuda_fp16.h>

#define Bn   4
#define Pn   900
#define Hn   8
#define DKn  64
#define DMn  512
#define PP2  (Pn*Pn)      // 810000
#define BHn  (Bn*Hn)      // 32

typedef unsigned long long u64_t;

// ---- fp16 m16n8k16 MMA ----
__device__ __forceinline__ void mma_f16_k16(float* c, const unsigned* a, const unsigned* b) {
    asm("mma.sync.aligned.m16n8k16.row.col.f32.f16.f16.f32 "
        "{%0,%1,%2,%3}, {%4,%5,%6,%7}, {%8,%9}, {%0,%1,%2,%3};"
        : "+f"(c[0]), "+f"(c[1]), "+f"(c[2]), "+f"(c[3])
        : "r"(a[0]), "r"(a[1]), "r"(a[2]), "r"(a[3]), "r"(b[0]), "r"(b[1]));
}
// A-fragment from two u64 loads: l0 @ row qr gives (a0,a2), l1 @ row qr+8 gives (a1,a3)
__device__ __forceinline__ void mma_from(float* c, u64_t l0, u64_t l1, const unsigned* b) {
    unsigned a[4] = { (unsigned)l0, (unsigned)l1,
                      (unsigned)(l0 >> 32), (unsigned)(l1 >> 32) };
    mma_f16_k16(c, a, b);
}
__device__ __forceinline__ unsigned packh2(float x, float y) {
    __half2 h = __floats2half2_rn(x, y);
    return *reinterpret_cast<unsigned*>(&h);
}
// split (v0,v1) into fp16 hi pair + fp16 lo pair (11+11 mantissa bits)
__device__ __forceinline__ void split2(float v0, float v1, unsigned& hi, unsigned& lo) {
    __half h0 = __float2half_rn(v0), h1 = __float2half_rn(v1);
    float r0 = v0 - __half2float(h0), r1 = v1 - __half2float(h1);
    __half2 H = __halves2half2(h0, h1);
    hi = *reinterpret_cast<unsigned*>(&H);
    lo = packh2(r0, r1);
}

// order-preserving float->uint
__device__ __forceinline__ unsigned ord_f(float v) {
    unsigned b = __float_as_uint(v);
    return (b & 0x80000000u) ? ~b : (b | 0x80000000u);
}
__device__ __forceinline__ u64_t amax_key(float v, int p) {
    return ((u64_t)ord_f(v) << 32) | (u64_t)(0xFFFFFFFFu - (unsigned)p);
}

// ---- scratch (static device allocations; no runtime alloc) ----
__device__ unsigned g_Qh[BHn*Pn*32];
__device__ unsigned g_Ql[BHn*Pn*32];
__device__ unsigned g_Kh[BHn*Pn*32];
__device__ unsigned g_Kl[BHn*Pn*32];
__device__ float    g_S [BHn*PP2];
__device__ u64_t    g_AMX[BHn*Pn];
__device__ unsigned g_ATT[Bn*4*PP2];
__device__ float    g_PART[Bn*Hn*Pn*64];

// ============================================================
// K1: projection GEMM (Q and K via blockIdx.z), fp16 3-MMA split.
// ============================================================
__global__ __launch_bounds__(256) void proj_kernel(const float* __restrict__ query,
                                                   const float* __restrict__ key_t,
                                                   const float* __restrict__ Wq,
                                                   const float* __restrict__ bq,
                                                   const float* __restrict__ Wk,
                                                   const float* __restrict__ bk)
{
    __shared__ unsigned Ahi[64*20], Alo[64*20], Whi[64*20], Wlo[64*20];
    const int z = blockIdx.z;
    const float* A    = z ? key_t : query;
    const float* W    = z ? Wk : Wq;
    const float* bias = z ? bk : bq;
    unsigned* outh = z ? g_Kh : g_Qh;
    unsigned* outl = z ? g_Kl : g_Ql;

    const int bm = blockIdx.y * 64;
    const int bn = blockIdx.x * 64;
    const int tid = threadIdx.x;
    const int lane = tid & 31, wid = tid >> 5;
    const int qr = lane >> 2, icb = lane & 3;
    const int m0 = (wid & 3) * 16;
    const int n0 = (wid >> 2) * 32;
    float acc[4][4] = {};

    for (int k0 = 0; k0 < DMn; k0 += 32) {
        #pragma unroll
        for (int i = tid; i < 1024; i += 256) {
            int r = i >> 4, c2 = i & 15;
            int m = bm + r;
            int kc = k0 + 2*c2;
            float a0 = 0.f, a1 = 0.f;
            if (m < Bn*Pn) {
                a0 = A[(size_t)m*DMn + kc];
                a1 = A[(size_t)m*DMn + kc + 1];
            }
            float w0 = W[(size_t)(bn + r)*DMn + kc];
            float w1 = W[(size_t)(bn + r)*DMn + kc + 1];
            split2(a0, a1, Ahi[r*20 + c2], Alo[r*20 + c2]);
            split2(w0, w1, Whi[r*20 + c2], Wlo[r*20 + c2]);
        }
        __syncthreads();
        #pragma unroll
        for (int ks = 0; ks < 2; ks++) {
            int b8 = ks*8;
            unsigned ah[4], al[4];
            int rA = (m0 + qr)*20 + b8 + icb;
            int rB = (m0 + qr + 8)*20 + b8 + icb;
            ah[0] = Ahi[rA];     ah[1] = Ahi[rB];
            ah[2] = Ahi[rA + 4]; ah[3] = Ahi[rB + 4];
            al[0] = Alo[rA];     al[1] = Alo[rB];
            al[2] = Alo[rA + 4]; al[3] = Alo[rB + 4];
            #pragma unroll
            for (int j = 0; j < 4; j++) {
                int rK = (n0 + j*8 + qr)*20 + b8 + icb;
                unsigned bh_[2] = { Whi[rK], Whi[rK + 4] };
                unsigned bl_[2] = { Wlo[rK], Wlo[rK + 4] };
                mma_f16_k16(acc[j], ah, bh_);
                mma_f16_k16(acc[j], ah, bl_);
                mma_f16_k16(acc[j], al, bh_);
            }
        }
        __syncthreads();
    }

    const int mA = bm + m0 + qr, mB = mA + 8;
    #pragma unroll
    for (int j = 0; j < 4; j++) {
        int na = bn + n0 + j*8 + 2*icb;
        int h = na >> 6, c2 = (na & 63) >> 1;
        if (mA < Bn*Pn) {
            int b = mA / Pn, p = mA % Pn;
            unsigned hi, lo;
            split2(acc[j][0] + bias[na], acc[j][1] + bias[na+1], hi, lo);
            size_t idx = ((size_t)(b*Hn + h)*Pn + p)*32 + c2;
            outh[idx] = hi; outl[idx] = lo;
        }
        if (mB < Bn*Pn) {
            int b = mB / Pn, p = mB % Pn;
            unsigned hi, lo;
            split2(acc[j][2] + bias[na], acc[j][3] + bias[na+1], hi, lo);
            size_t idx = ((size_t)(b*Hn + h)*Pn + p)*32 + c2;
            outh[idx] = hi; outl[idx] = lo;
        }
    }
}

// ============================================================
// K2: scores via fp16 3-MMA split (k16) + fused argmax.
// ============================================================
__global__ __launch_bounds__(256) void scores_kernel()
{
    __shared__ unsigned Qhi[64*36], Qlo[64*36], Khi[64*36], Klo[64*36];

    const int bh = blockIdx.z;
    const int p0 = blockIdx.y*64, q0 = blockIdx.x*64;
    const int tid = threadIdx.x;
    const int lane = tid & 31, wid = tid >> 5;
    const int qr = lane >> 2, icb = lane & 3;

    #pragma unroll
    for (int i = tid; i < 2048; i += 256) {
        int r = i >> 5, c2 = i & 31;
        unsigned qh = 0, ql = 0, kh = 0, kl = 0;
        if (p0 + r < Pn) {
            size_t idx = ((size_t)bh*Pn + p0 + r)*32 + c2;
            qh = g_Qh[idx]; ql = g_Ql[idx];
        }
        if (q0 + r < Pn) {
            size_t idx = ((size_t)bh*Pn + q0 + r)*32 + c2;
            kh = g_Kh[idx]; kl = g_Kl[idx];
        }
        Qhi[r*36 + c2] = qh; Qlo[r*36 + c2] = ql;
        Khi[r*36 + c2] = kh; Klo[r*36 + c2] = kl;
    }
    __syncthreads();

    const int m0 = (wid & 3) * 16;
    const int n0 = (wid >> 2) * 32;
    float acc[4][4] = {};

    #pragma unroll
    for (int ks = 0; ks < 4; ks++) {
        int b8 = ks*8;
        unsigned ah[4], al[4];
        int rA = (m0 + qr)*36 + b8 + icb;
        int rB = (m0 + qr + 8)*36 + b8 + icb;
        ah[0] = Qhi[rA];     ah[1] = Qhi[rB];
        ah[2] = Qhi[rA + 4]; ah[3] = Qhi[rB + 4];
        al[0] = Qlo[rA];     al[1] = Qlo[rB];
        al[2] = Qlo[rA + 4]; al[3] = Qlo[rB + 4];
        #pragma unroll
        for (int j = 0; j < 4; j++) {
            int rK = (n0 + j*8 + qr)*36 + b8 + icb;
            unsigned bh_[2] = { Khi[rK], Khi[rK + 4] };
            unsigned bl_[2] = { Klo[rK], Klo[rK + 4] };
            mma_f16_k16(acc[j], ah, bh_);
            mma_f16_k16(acc[j], ah, bl_);
            mma_f16_k16(acc[j], al, bh_);
        }
    }

    float* Sb = g_S + (size_t)bh*PP2;
    const int pA = p0 + m0 + qr, pB = pA + 8;
    const bool vA = pA < Pn, vB = pB < Pn;
    #pragma unroll
    for (int j = 0; j < 4; j++) {
        int qa = q0 + n0 + j*8 + 2*icb;
        int qb = qa + 1;
        if (vA) {
            if (qa < Pn) Sb[pA*Pn + qa] = acc[j][0];
            if (qb < Pn) Sb[pA*Pn + qb] = acc[j][1];
        }
        if (vB) {
            if (qa < Pn) Sb[pB*Pn + qa] = acc[j][2];
            if (qb < Pn) Sb[pB*Pn + qb] = acc[j][3];
        }
        u64_t ka = 0, kb = 0;
        if (vA) { ka = amax_key(acc[j][0], pA); kb = amax_key(acc[j][1], pA); }
        if (vB) {
            u64_t t = amax_key(acc[j][2], pB); if (t > ka) ka = t;
            t = amax_key(acc[j][3], pB);       if (t > kb) kb = t;
        }
        #pragma unroll
        for (int m = 4; m <= 16; m <<= 1) {
            u64_t ta = __shfl_xor_sync(0xFFFFFFFFu, ka, m);
            u64_t tb = __shfl_xor_sync(0xFFFFFFFFu, kb, m);
            if (ta > ka) ka = ta;
            if (tb > kb) kb = tb;
        }
        if (qr == 0) {
            if (qa < Pn) atomicMax(&g_AMX[bh*Pn + qa], ka);
            if (qb < Pn) atomicMax(&g_AMX[bh*Pn + qb], kb);
        }
    }
}

// ============================================================
// K4: gaussian + scale + softmax; warp = one p-row of a CHANNEL PAIR.
// ============================================================
__global__ __launch_bounds__(256) void modsm_kernel()
{
    __shared__ float sT[900];
    __shared__ unsigned char sFX0[900], sFY0[900], sFX1[900], sFY1[900];
    const int bj = blockIdx.y;
    const int b = bj >> 2, j = bj & 3;
    const int bh0 = b*Hn + 2*j, bh1 = bh0 + 1;
    const int p0 = blockIdx.x * 8;
    const int tid = threadIdx.x, lane = tid & 31, wrp = tid >> 5;

    for (int i = tid; i < 900; i += 256) {
        int a = i / 30, bc = i - (i/30)*30;
        float d = (-1.f + (2.f/29.f)*(float)a) - (float)bc;
        sT[i] = __expf(-d*d*0.02f);
        unsigned id0 = 0xFFFFFFFFu - (unsigned)(g_AMX[bh0*Pn + i] & 0xFFFFFFFFu);
        unsigned id1 = 0xFFFFFFFFu - (unsigned)(g_AMX[bh1*Pn + i] & 0xFFFFFFFFu);
        sFX0[i] = (unsigned char)(id0 % 30); sFY0[i] = (unsigned char)(id0 / 30);
        sFX1[i] = (unsigned char)(id1 % 30); sFY1[i] = (unsigned char)(id1 / 30);
    }
    __syncthreads();

    const int p = p0 + wrp;
    if (p >= Pn) return;
    const float* S0 = g_S + (size_t)bh0*PP2 + (size_t)p*Pn;
    const float* S1 = g_S + (size_t)bh1*PP2 + (size_t)p*Pn;
    const float* Tx = sT + (p % 30)*30;
    const float* Ty = sT + (p / 30)*30;

    float v0[29], v1[29];
    float m0 = -1e30f, m1 = -1e30f;
    #pragma unroll
    for (int i = 0; i < 29; i++) {
        int q = lane + i*32;
        if (q < Pn) {
            float s0 = S0[q], s1 = S1[q];
            float g0 = Tx[sFX0[q]] * Ty[sFY0[q]];
            float g1 = Tx[sFX1[q]] * Ty[sFY1[q]];
            v0[i] = g0 * s0 * 0.125f;
            v1[i] = g1 * s1 * 0.125f;
            m0 = fmaxf(m0, v0[i]);
            m1 = fmaxf(m1, v1[i]);
        } else { v0[i] = -1e30f; v1[i] = -1e30f; }
    }
    #pragma unroll
    for (int m = 16; m > 0; m >>= 1) {
        m0 = fmaxf(m0, __shfl_xor_sync(0xFFFFFFFFu, m0, m));
        m1 = fmaxf(m1, __shfl_xor_sync(0xFFFFFFFFu, m1, m));
    }

    float sum0 = 0.f, sum1 = 0.f;
    #pragma unroll
    for (int i = 0; i < 29; i++) {
        float e0 = __expf(v0[i] - m0);
        float e1 = __expf(v1[i] - m1);
        v0[i] = e0; v1[i] = e1;
        if (lane + i*32 < Pn) { sum0 += e0; sum1 += e1; }
    }
    #pragma unroll
    for (int m = 16; m > 0; m >>= 1) {
        sum0 += __shfl_xor_sync(0xFFFFFFFFu, sum0, m);
        sum1 += __shfl_xor_sync(0xFFFFFFFFu, sum1, m);
    }
    const float inv0 = 1.f / sum0, inv1 = 1.f / sum1;
    unsigned* dst = g_ATT + (size_t)bj*PP2 + (size_t)p*Pn;
    #pragma unroll
    for (int i = 0; i < 29; i++) {
        int q = lane + i*32;
        if (q < Pn) dst[q] = packh2(v0[i]*inv0, v1[i]*inv1);
    }
}

// ============================================================
// K5: FUSED conv1+conv2+value-einsum, fp16 MMA.
// R12 loop structure; sMid u64-packed [plane(kc*4+icb)][pos] stride 612
// (stride mod 16 = 4 -> LDS.64 conflict-free in both half-warp phases).
// Phase 2: 2 LDS.64 per MMA (was 4 scalar LDS), no register caching.
// ============================================================
#define FT_Y   16
#define FT_X   32
#define MID_W  34
#define MID_N  612
#define IN_W   36
#define IN_N   720
#define PIN    728
#define SMEM_FUSED (4*PIN*4 + 8*MID_N*8)   // 11648 + 39168 = 50816 B

__global__ __launch_bounds__(256) void fused_conv_kernel(const float* __restrict__ w1,
                                                         const float* __restrict__ b1,
                                                         const float* __restrict__ w2,
                                                         const float* __restrict__ b2,
                                                         const float* __restrict__ value)
{
    extern __shared__ unsigned dsm[];
    unsigned* sIn    = dsm;                                       // 4 ic-pairs x 728
    u64_t*    sMid64 = reinterpret_cast<u64_t*>(dsm + 4*PIN);     // 8 planes x 612
    __shared__ float sB1[32];
    __shared__ float sB2[8];
    __shared__ float sVal[32];

    const int n  = blockIdx.z;
    const int X0 = blockIdx.x * FT_X;
    const int Y0 = blockIdx.y * FT_Y;
    const int tid  = threadIdx.x;
    const int lane = tid & 31, wid = tid >> 5;
    const int qr = lane >> 2, icb = lane & 3;

    if (tid < 32) {
        sB1[tid] = b1[tid];
        sVal[tid] = (X0 + tid < Pn) ? value[n*Pn + X0 + tid] : 0.f;
    }
    if (tid < 8)  sB2[tid] = b2[tid];

    for (int i = tid; i < IN_N; i += 256) {
        int r = i / IN_W, c = i - r*IN_W;
        int gy = Y0 - 2 + r, gx = X0 - 2 + c;
        bool ok = (gy >= 0 && gy < Pn && gx >= 0 && gx < Pn);
        size_t base = (size_t)gy*Pn + gx;
        #pragma unroll
        for (int j = 0; j < 4; j++)
            sIn[j*PIN + i] = ok ? g_ATT[(size_t)(n*4 + j)*PP2 + base] : 0u;
    }

    unsigned bw[5][4][2];
    #pragma unroll
    for (int p = 0; p < 5; p++) {
        int sA = 2*p, sB = 2*p + 1;
        #pragma unroll
        for (int g = 0; g < 4; g++) {
            int oc = g*8 + qr;
            bw[p][g][0] = packh2(w1[(oc*8 + 2*icb)*9 + sA],
                                 w1[(oc*8 + 2*icb + 1)*9 + sA]);
            bw[p][g][1] = (sB < 9) ? packh2(w1[(oc*8 + 2*icb)*9 + sB],
                                            w1[(oc*8 + 2*icb + 1)*9 + sB])
                                   : 0u;
        }
    }
    __syncthreads();

    // ---- phase 1: conv1 -> sMid64 ----
    for (int t = wid; t < 39; t += 8) {
        int pr0 = t*16 + qr;
        int pr1 = pr0 + 8;
        int q0 = pr0 < MID_N ? pr0 : MID_N - 1;
        int q1 = pr1 < MID_N ? pr1 : MID_N - 1;
        int my0 = q0 / MID_W, mx0 = q0 - my0*MID_W;
        int my1 = q1 / MID_W, mx1 = q1 - my1*MID_W;
        int base0 = my0*IN_W + mx0;
        int base1 = my1*IN_W + mx1;
        float acc[4][4] = {};
        #pragma unroll
        for (int p = 0; p < 5; p++) {
            int sA = 2*p, sB = 2*p + 1;
            int offA = (sA/3)*IN_W + (sA - (sA/3)*3);
            int offB = (sB < 9) ? (sB/3)*IN_W + (sB - (sB/3)*3) : offA;
            unsigned a[4];
            a[0] = sIn[icb*PIN + base0 + offA];
            a[1] = sIn[icb*PIN + base1 + offA];
            a[2] = sIn[icb*PIN + base0 + offB];
            a[3] = sIn[icb*PIN + base1 + offB];
            #pragma unroll
            for (int g = 0; g < 4; g++) mma_f16_k16(acc[g], a, bw[p][g]);
        }
        bool s0 = pr0 < MID_N, s1 = pr1 < MID_N;
        int gy0 = Y0 - 1 + my0, gx0 = X0 - 1 + mx0;
        int gy1 = Y0 - 1 + my1, gx1 = X0 - 1 + mx1;
        bool in0 = (gy0 >= 0 && gy0 < Pn && gx0 >= 0 && gx0 < Pn);
        bool in1 = (gy1 >= 0 && gy1 < Pn && gx1 >= 0 && gx1 < Pn);
        // u64 store: plane kc*4+icb; low = oc pair (16kc+2icb), high = pair (+8)
        #pragma unroll
        for (int kc = 0; kc < 2; kc++) {
            int ocL = kc*16 + 2*icb;
            int ocH = ocL + 8;
            if (s0) {
                float vL0 = in0 ? fmaxf(acc[2*kc][0]   + sB1[ocL],   0.f) : 0.f;
                float vL1 = in0 ? fmaxf(acc[2*kc][1]   + sB1[ocL+1], 0.f) : 0.f;
                float vH0 = in0 ? fmaxf(acc[2*kc+1][0] + sB1[ocH],   0.f) : 0.f;
                float vH1 = in0 ? fmaxf(acc[2*kc+1][1] + sB1[ocH+1], 0.f) : 0.f;
                sMid64[(kc*4 + icb)*MID_N + q0] =
                    (u64_t)packh2(vL0, vL1) | ((u64_t)packh2(vH0, vH1) << 32);
            }
            if (s1) {
                float vL2 = in1 ? fmaxf(acc[2*kc][2]   + sB1[ocL],   0.f) : 0.f;
                float vL3 = in1 ? fmaxf(acc[2*kc][3]   + sB1[ocL+1], 0.f) : 0.f;
                float vH2 = in1 ? fmaxf(acc[2*kc+1][2] + sB1[ocH],   0.f) : 0.f;
                float vH3 = in1 ? fmaxf(acc[2*kc+1][3] + sB1[ocH+1], 0.f) : 0.f;
                sMid64[(kc*4 + icb)*MID_N + q1] =
                    (u64_t)packh2(vL2, vL3) | ((u64_t)packh2(vH2, vH3) << 32);
            }
        }
    }
    __syncthreads();

    unsigned bw2[9][2][2];
    #pragma unroll
    for (int s = 0; s < 9; s++)
        #pragma unroll
        for (int kc = 0; kc < 2; kc++) {
            bw2[s][kc][0] = packh2(w2[(qr*32 + 16*kc + 2*icb)*9 + s],
                                   w2[(qr*32 + 16*kc + 2*icb + 1)*9 + s]);
            bw2[s][kc][1] = packh2(w2[(qr*32 + 16*kc + 8 + 2*icb)*9 + s],
                                   w2[(qr*32 + 16*kc + 8 + 2*icb + 1)*9 + s]);
        }

    // ---- phase 2: conv2 + value reduction (R12 loop, u64 A-loads) ----
    for (int t = wid; t < 32; t += 8) {
        int oy = t >> 1;
        int ox0 = (t & 1)*16 + qr, ox1 = ox0 + 8;
        float acc[4] = {};
        #pragma unroll
        for (int ky = 0; ky < 3; ky++) {
            #pragma unroll
            for (int kx = 0; kx < 3; kx++) {
                int r0 = (oy + ky)*MID_W + ox0 + kx;
                int r1 = (oy + ky)*MID_W + ox1 + kx;
                int s = ky*3 + kx;
                #pragma unroll
                for (int kc = 0; kc < 2; kc++) {
                    u64_t l0 = sMid64[(kc*4 + icb)*MID_N + r0];
                    u64_t l1 = sMid64[(kc*4 + icb)*MID_N + r1];
                    mma_from(acc, l0, l1, bw2[s][kc]);
                }
            }
        }
        int oc = 2*icb;
        float bb0 = sB2[oc], bb1 = sB2[oc+1];
        float svA = sVal[ox0], svB = sVal[ox1];
        float r0 = fmaxf(acc[0] + bb0, 0.f);
        float r1 = fmaxf(acc[1] + bb1, 0.f);
        float r2 = fmaxf(acc[2] + bb0, 0.f);
        float r3 = fmaxf(acc[3] + bb1, 0.f);
        float s0 = r0*svA + r2*svB;
        float s1 = r1*svA + r3*svB;
        #pragma unroll
        for (int m = 4; m <= 16; m <<= 1) {
            s0 += __shfl_xor_sync(0xFFFFFFFFu, s0, m);
            s1 += __shfl_xor_sync(0xFFFFFFFFu, s1, m);
        }
        int y = Y0 + oy;
        if (qr == 0 && y < Pn) {
            int xp = blockIdx.x*2 + (t & 1);
            g_PART[((size_t)(n*Hn + oc    )*Pn + y)*64 + xp] = s0;
            g_PART[((size_t)(n*Hn + oc + 1)*Pn + y)*64 + xp] = s1;
        }
    }
}

// ============================================================
// K6: reduce partials -> out[b,p] = mean_h sum_xp
// ============================================================
__global__ __launch_bounds__(128) void reduce_kernel(float* __restrict__ out)
{
    const int bp = blockIdx.x;
    const int b = bp / Pn, p = bp % Pn;
    const int tid = threadIdx.x;
    float s = 0.f;
    for (int i = tid; i < 512; i += 128) {
        int h = i >> 6, xp = i & 63;
        if (xp < 58)
            s += g_PART[((size_t)(b*Hn + h)*Pn + p)*64 + xp];
    }
    __shared__ float red[128];
    red[tid] = s; __syncthreads();
    for (int st = 64; st > 0; st >>= 1) {
        if (tid < st) red[tid] += red[tid + st];
        __syncthreads();
    }
    if (tid == 0) out[bp] = red[0] * 0.125f;
}

// ============================================================
extern "C" void kernel_launch(void* const* d_in, const int* in_sizes, int n_in,
                              void* d_out, int out_size)
{
    const float* query = (const float*)d_in[0];
    const float* key_t = (const float*)d_in[1];
    const float* value = (const float*)d_in[2];
    const float* Wq    = (const float*)d_in[3];
    const float* bq    = (const float*)d_in[4];
    const float* Wk    = (const float*)d_in[5];
    const float* bk    = (const float*)d_in[6];
    const float* c1w   = (const float*)d_in[7];
    const float* c1b   = (const float*)d_in[8];
    const float* c2w   = (const float*)d_in[9];
    const float* c2b   = (const float*)d_in[10];
    float* out = (float*)d_out;

    static int smem_set = 0;
    if (!smem_set) {
        cudaFuncSetAttribute(fused_conv_kernel,
                             cudaFuncAttributeMaxDynamicSharedMemorySize, SMEM_FUSED);
        smem_set = 1;
    }

    proj_kernel<<<dim3(8, 57, 2), 256>>>(query, key_t, Wq, bq, Wk, bk);
    scores_kernel<<<dim3(15, 15, 32), 256>>>();
    modsm_kernel<<<dim3(113, 16), 256>>>();
    fused_conv_kernel<<<dim3(29, 57, 4), 256, SMEM_FUSED>>>(c1w, c1b, c2w, c2b, value);
    reduce_kernel<<<dim3(Bn*Pn), 128>>>(out);
}